// round 1
// baseline (speedup 1.0000x reference)
#include <cuda_runtime.h>

#define NN 4096
#define DD 512
#define F1V 64
#define HH 4
#define MAXNBR 128

// ---------------- device scratch (static, no allocation) ----------------
__device__ int   g_cnt[NN];
__device__ int   g_cols[NN * MAXNBR];
__device__ float g_Wh[HH * NN * F1V];     // [h][n][64]
__device__ float g_src[HH * NN];
__device__ float g_dst[HH * NN];
__device__ float g_cat[NN * HH * F1V];    // [n][h*64+f]
__device__ float g_Whc[NN * F1V];
__device__ float g_srcc[NN];
__device__ float g_dstc[NN];
__device__ float g_gc[NN * F1V];
__device__ float g_t1[NN * 32];
__device__ float g_h1[NN * 32];
__device__ float g_t23[NN * 32];          // [n][0:16]=t2(mu pre-agg), [n][16:32]=t3
__device__ float g_z[NN * 16];

// ---------------- 1: CSR build (warp per row, order-deterministic) ------
__global__ void k_build_csr(const float* __restrict__ adj) {
    int wid = threadIdx.x >> 5, lane = threadIdx.x & 31;
    int row = blockIdx.x * 8 + wid;
    const float4* arow = reinterpret_cast<const float4*>(adj + (size_t)row * NN);
    int cnt = 0;
    int* cols = g_cols + row * MAXNBR;
    for (int step = 0; step < 32; ++step) {
        float4 v = arow[step * 32 + lane];
        float vals[4] = {v.x, v.y, v.z, v.w};
        #pragma unroll
        for (int e = 0; e < 4; ++e) {
            bool p = vals[e] > 0.0f;
            unsigned m = __ballot_sync(0xffffffffu, p);
            if (p) {
                int pos = cnt + __popc(m & ((1u << lane) - 1u));
                if (pos < MAXNBR) cols[pos] = (step * 32 + lane) * 4 + e;
            }
            cnt += __popc(m);
        }
    }
    if (lane == 0) g_cnt[row] = cnt > MAXNBR ? MAXNBR : cnt;
}

// ---------------- 2: 64x64-tile fp32 GEMM, out cols = 64 ----------------
// sel 0: A=Aext(x), B=W_heads (per-head via blockIdx.y), C=g_Wh
// sel 1: A=g_cat,   B=W_att,                              C=g_Whc
__global__ void k_gemm64(const float* __restrict__ Aext, const float* __restrict__ B,
                         int K, int sel) {
    __shared__ float As[32 * 65];
    __shared__ float Bs[32 * 64];
    const float* A  = sel ? g_cat : Aext;
    const float* Bh = B + (sel ? 0 : (size_t)blockIdx.y * DD * F1V);
    float* Ch = sel ? g_Whc : (g_Wh + (size_t)blockIdx.y * NN * F1V);
    int m0 = blockIdx.x * 64;
    int tid = threadIdx.x;
    int ty = tid >> 4, tx = tid & 15;
    float acc[4][4] = {};
    for (int k0 = 0; k0 < K; k0 += 32) {
        #pragma unroll
        for (int i = 0; i < 8; ++i) {
            int l = tid + i * 256;
            int m = l >> 5, k = l & 31;
            As[k * 65 + m] = A[(size_t)(m0 + m) * K + k0 + k];
        }
        #pragma unroll
        for (int i = 0; i < 8; ++i) {
            int l = tid + i * 256;
            int k = l >> 6, c = l & 63;
            Bs[k * 64 + c] = Bh[(size_t)(k0 + k) * 64 + c];
        }
        __syncthreads();
        #pragma unroll
        for (int k = 0; k < 32; ++k) {
            float av[4], bv[4];
            #pragma unroll
            for (int i = 0; i < 4; ++i) av[i] = As[k * 65 + ty * 4 + i];
            #pragma unroll
            for (int j = 0; j < 4; ++j) bv[j] = Bs[k * 64 + tx * 4 + j];
            #pragma unroll
            for (int i = 0; i < 4; ++i)
                #pragma unroll
                for (int j = 0; j < 4; ++j)
                    acc[i][j] += av[i] * bv[j];
        }
        __syncthreads();
    }
    #pragma unroll
    for (int i = 0; i < 4; ++i) {
        int m = m0 + ty * 4 + i;
        #pragma unroll
        for (int j = 0; j < 4; ++j)
            Ch[(size_t)m * 64 + tx * 4 + j] = acc[i][j];
    }
}

// ---------------- 3: src/dst attention logits (warp per (h,n)) ----------
__global__ void k_srcdst(const float* __restrict__ a, int sel) {
    int wid = threadIdx.x >> 5, lane = threadIdx.x & 31;
    int wg = blockIdx.x * 8 + wid;
    int n = wg & (NN - 1);
    int h = wg >> 12;
    const float* Wh = sel ? g_Whc : g_Wh;
    float* src = sel ? g_srcc : g_src;
    float* dst = sel ? g_dstc : g_dst;
    const float* row = Wh + ((size_t)h * NN + n) * 64;
    const float* ah = a + h * 128;
    float w0 = row[lane], w1 = row[lane + 32];
    float s = w0 * ah[lane]      + w1 * ah[lane + 32];
    float d = w0 * ah[64 + lane] + w1 * ah[96 + lane];
    #pragma unroll
    for (int o = 16; o; o >>= 1) {
        s += __shfl_xor_sync(0xffffffffu, s, o);
        d += __shfl_xor_sync(0xffffffffu, d, o);
    }
    if (lane == 0) { src[h * NN + n] = s; dst[h * NN + n] = d; }
}

// ---------------- 4: sparse GAT softmax + aggregate + ELU ---------------
// warp per (row, head). sel 0: heads -> g_cat (stride 256); sel 1: att -> g_gc
__global__ void k_gat_aggr(int sel) {
    int wid = threadIdx.x >> 5, lane = threadIdx.x & 31;
    int wg = blockIdx.x * 8 + wid;
    int hShift = sel ? 0 : 2;
    int h = wg & ((1 << hShift) - 1);
    int row = wg >> hShift;
    const float* Wh  = sel ? g_Whc  : g_Wh;
    const float* src = sel ? g_srcc : g_src;
    const float* dst = sel ? g_dstc : g_dst;
    float* out = sel ? g_gc : g_cat;
    int outStride = sel ? 64 : 256;

    int cnt = g_cnt[row];
    const int* cols = g_cols + row * MAXNBR;
    float si = src[h * NN + row];
    const float* dsth = dst + (size_t)h * NN;

    float e[4]; int cl[4];
    float mx = -1e30f;
    #pragma unroll
    for (int t = 0; t < 4; ++t) {
        int idx = t * 32 + lane;
        if (idx < cnt) {
            int c = cols[idx];
            cl[t] = c;
            float v = si + dsth[c];
            v = v > 0.0f ? v : 0.2f * v;   // LeakyReLU
            e[t] = v;
            mx = fmaxf(mx, v);
        } else { e[t] = -1e30f; cl[t] = 0; }
    }
    #pragma unroll
    for (int o = 16; o; o >>= 1) mx = fmaxf(mx, __shfl_xor_sync(0xffffffffu, mx, o));
    float sum = 0.0f;
    #pragma unroll
    for (int t = 0; t < 4; ++t) {
        e[t] = (t * 32 + lane < cnt) ? __expf(e[t] - mx) : 0.0f;
        sum += e[t];
    }
    #pragma unroll
    for (int o = 16; o; o >>= 1) sum += __shfl_xor_sync(0xffffffffu, sum, o);
    float inv = 1.0f / sum;

    const float* Whh = Wh + (size_t)h * NN * 64;
    float a0 = 0.0f, a1 = 0.0f;
    for (int t = 0; t * 32 < cnt; ++t) {
        int lim = cnt - t * 32; if (lim > 32) lim = 32;
        for (int l = 0; l < lim; ++l) {
            float w = __shfl_sync(0xffffffffu, e[t], l);
            int   c = __shfl_sync(0xffffffffu, cl[t], l);
            const float* wr = Whh + (size_t)c * 64;
            a0 += w * wr[lane];
            a1 += w * wr[lane + 32];
        }
    }
    a0 *= inv; a1 *= inv;
    a0 = a0 > 0.0f ? a0 : __expf(a0) - 1.0f;   // ELU
    a1 = a1 > 0.0f ? a1 : __expf(a1) - 1.0f;
    float* orow = out + (size_t)row * outStride + h * 64;
    orow[lane] = a0;
    orow[lane + 32] = a1;
}

// ---------------- 5: t1 = gc_att @ W1 (warp per row, 64x32) -------------
__global__ void k_t1(const float* __restrict__ W1) {
    int wid = threadIdx.x >> 5, lane = threadIdx.x & 31;
    int row = blockIdx.x * 8 + wid;
    const float* g = g_gc + (size_t)row * 64;
    float r0 = g[lane], r1 = g[lane + 32];
    float acc = 0.0f;
    #pragma unroll
    for (int k = 0; k < 64; ++k) {
        float gv = __shfl_sync(0xffffffffu, (k < 32) ? r0 : r1, k & 31);
        acc += gv * W1[k * 32 + lane];
    }
    g_t1[(size_t)row * 32 + lane] = acc;
}

// ---------------- 6: h1 = relu(neighbor_sum(t1)) ------------------------
__global__ void k_nbrsum_h1() {
    int wid = threadIdx.x >> 5, lane = threadIdx.x & 31;
    int row = blockIdx.x * 8 + wid;
    int cnt = g_cnt[row];
    const int* cols = g_cols + row * MAXNBR;
    float acc = 0.0f;
    for (int j = 0; j < cnt; ++j) {
        int c = cols[j];
        acc += g_t1[(size_t)c * 32 + lane];
    }
    g_h1[(size_t)row * 32 + lane] = fmaxf(acc, 0.0f);
}

// ---------------- 7: t2 = h1@W2, t3 = h1@W3 (warp per row) --------------
__global__ void k_t23(const float* __restrict__ W2, const float* __restrict__ W3) {
    int wid = threadIdx.x >> 5, lane = threadIdx.x & 31;
    int row = blockIdx.x * 8 + wid;
    float hv = g_h1[(size_t)row * 32 + lane];
    const float* W = (lane < 16) ? W2 : W3;
    int f = lane & 15;
    float acc = 0.0f;
    #pragma unroll
    for (int k = 0; k < 32; ++k) {
        float h = __shfl_sync(0xffffffffu, hv, k);
        acc += h * W[k * 16 + f];
    }
    g_t23[(size_t)row * 32 + lane] = acc;
}

// ---------------- 8: mu/logvar = nbrsum, z = eps*exp(lv)+mu, write ------
__global__ void k_final(const float* __restrict__ eps, float* __restrict__ out) {
    int wid = threadIdx.x >> 5, lane = threadIdx.x & 31;
    int row = blockIdx.x * 8 + wid;
    int cnt = g_cnt[row];
    const int* cols = g_cols + row * MAXNBR;
    float acc = 0.0f;
    for (int j = 0; j < cnt; ++j) {
        int c = cols[j];
        acc += g_t23[(size_t)c * 32 + lane];
    }
    float other = __shfl_xor_sync(0xffffffffu, acc, 16);
    size_t NNq = (size_t)NN * NN;
    if (lane < 16) {
        out[NNq + (size_t)row * 16 + lane] = acc;                     // mu
        float zz = eps[(size_t)row * 16 + lane] * __expf(other) + acc;
        g_z[(size_t)row * 16 + lane] = zz;
    } else {
        out[NNq + (size_t)NN * 16 + (size_t)row * 16 + (lane - 16)] = acc; // logvar
    }
}

// ---------------- 9: adj_rec = z @ z^T (64x64 tiles, float4 stores) -----
__global__ void k_adjrec(float* __restrict__ out) {
    __shared__ float zi[64 * 17];
    __shared__ float zj[64 * 17];
    int i0 = blockIdx.y * 64, j0 = blockIdx.x * 64;
    int tid = threadIdx.x;
    for (int l = tid; l < 1024; l += 256) {
        int r = l >> 4, k = l & 15;
        zi[r * 17 + k] = g_z[(size_t)(i0 + r) * 16 + k];
        zj[r * 17 + k] = g_z[(size_t)(j0 + r) * 16 + k];
    }
    __syncthreads();
    int ty = tid >> 4, tx = tid & 15;
    float acc[4][4] = {};
    #pragma unroll
    for (int k = 0; k < 16; ++k) {
        float av[4], bv[4];
        #pragma unroll
        for (int i = 0; i < 4; ++i) av[i] = zi[(ty * 4 + i) * 17 + k];
        #pragma unroll
        for (int j = 0; j < 4; ++j) bv[j] = zj[(tx * 4 + j) * 17 + k];
        #pragma unroll
        for (int i = 0; i < 4; ++i)
            #pragma unroll
            for (int j = 0; j < 4; ++j)
                acc[i][j] += av[i] * bv[j];
    }
    #pragma unroll
    for (int i = 0; i < 4; ++i) {
        float4 v = make_float4(acc[i][0], acc[i][1], acc[i][2], acc[i][3]);
        *reinterpret_cast<float4*>(out + (size_t)(i0 + ty * 4 + i) * NN + j0 + tx * 4) = v;
    }
}

// ---------------- launch ------------------------------------------------
extern "C" void kernel_launch(void* const* d_in, const int* in_sizes, int n_in,
                              void* d_out, int out_size) {
    const float* x       = (const float*)d_in[0];
    const float* adj     = (const float*)d_in[1];
    const float* W_heads = (const float*)d_in[2];
    const float* a_heads = (const float*)d_in[3];
    const float* W_att   = (const float*)d_in[4];
    const float* a_att   = (const float*)d_in[5];
    const float* W1      = (const float*)d_in[6];
    const float* W2      = (const float*)d_in[7];
    const float* W3      = (const float*)d_in[8];
    const float* eps     = (const float*)d_in[9];
    float* out = (float*)d_out;
    (void)in_sizes; (void)n_in; (void)out_size;

    k_build_csr<<<NN / 8, 256>>>(adj);
    k_gemm64<<<dim3(NN / 64, HH), 256>>>(x, W_heads, DD, 0);
    k_srcdst<<<(NN * HH) / 8, 256>>>(a_heads, 0);
    k_gat_aggr<<<(NN * HH) / 8, 256>>>(0);
    k_gemm64<<<dim3(NN / 64, 1), 256>>>(nullptr, W_att, HH * F1V, 1);
    k_srcdst<<<NN / 8, 256>>>(a_att, 1);
    k_gat_aggr<<<NN / 8, 256>>>(1);
    k_t1<<<NN / 8, 256>>>(W1);
    k_nbrsum_h1<<<NN / 8, 256>>>();
    k_t23<<<NN / 8, 256>>>(W2, W3);
    k_final<<<NN / 8, 256>>>(eps, out);
    k_adjrec<<<dim3(NN / 64, NN / 64), 256>>>(out);
}

// round 2
// speedup vs baseline: 1.1414x; 1.1414x over previous
#include <cuda_runtime.h>

#define NN 4096
#define DD 512
#define F1V 64
#define HH 4
#define MAXNBR 128

// ---------------- device scratch (static, no allocation) ----------------
__device__ int   g_cnt[NN];
__device__ int   g_cols[NN * MAXNBR];
__device__ float g_Wh[HH * NN * F1V];     // [h][n][64]
__device__ float g_src[HH * NN];
__device__ float g_dst[HH * NN];
__device__ float g_cat[NN * HH * F1V];    // [n][h*64+f]
__device__ float g_Whc[NN * F1V];
__device__ float g_srcc[NN];
__device__ float g_dstc[NN];
__device__ float g_t1[NN * 32];
__device__ float g_t23[NN * 32];          // [n][0:16]=t2(mu pre-agg), [n][16:32]=t3
__device__ float g_z[NN * 16];

// ---------------- 1: CSR build (warp per row, order-deterministic) ------
__global__ void k_build_csr(const float* __restrict__ adj) {
    int wid = threadIdx.x >> 5, lane = threadIdx.x & 31;
    int row = blockIdx.x * 8 + wid;
    const float4* arow = reinterpret_cast<const float4*>(adj + (size_t)row * NN);
    int cnt = 0;
    int* cols = g_cols + row * MAXNBR;
    for (int step = 0; step < 32; ++step) {
        float4 v = arow[step * 32 + lane];
        float vals[4] = {v.x, v.y, v.z, v.w};
        #pragma unroll
        for (int e = 0; e < 4; ++e) {
            bool p = vals[e] > 0.0f;
            unsigned m = __ballot_sync(0xffffffffu, p);
            if (p) {
                int pos = cnt + __popc(m & ((1u << lane) - 1u));
                if (pos < MAXNBR) cols[pos] = (step * 32 + lane) * 4 + e;
            }
            cnt += __popc(m);
        }
    }
    if (lane == 0) g_cnt[row] = cnt > MAXNBR ? MAXNBR : cnt;
}

// ---------------- 2: 64x64-tile fp32 GEMM, out cols = 64 ----------------
__global__ void k_gemm64(const float* __restrict__ Aext, const float* __restrict__ B,
                         int K, int sel) {
    __shared__ float As[32 * 65];
    __shared__ float Bs[32 * 64];
    const float* A  = sel ? g_cat : Aext;
    const float* Bh = B + (sel ? 0 : (size_t)blockIdx.y * DD * F1V);
    float* Ch = sel ? g_Whc : (g_Wh + (size_t)blockIdx.y * NN * F1V);
    int m0 = blockIdx.x * 64;
    int tid = threadIdx.x;
    int ty = tid >> 4, tx = tid & 15;
    float acc[4][4] = {};
    for (int k0 = 0; k0 < K; k0 += 32) {
        #pragma unroll
        for (int i = 0; i < 8; ++i) {
            int l = tid + i * 256;
            int m = l >> 5, k = l & 31;
            As[k * 65 + m] = A[(size_t)(m0 + m) * K + k0 + k];
        }
        #pragma unroll
        for (int i = 0; i < 8; ++i) {
            int l = tid + i * 256;
            int k = l >> 6, c = l & 63;
            Bs[k * 64 + c] = Bh[(size_t)(k0 + k) * 64 + c];
        }
        __syncthreads();
        #pragma unroll
        for (int k = 0; k < 32; ++k) {
            float av[4], bv[4];
            #pragma unroll
            for (int i = 0; i < 4; ++i) av[i] = As[k * 65 + ty * 4 + i];
            #pragma unroll
            for (int j = 0; j < 4; ++j) bv[j] = Bs[k * 64 + tx * 4 + j];
            #pragma unroll
            for (int i = 0; i < 4; ++i)
                #pragma unroll
                for (int j = 0; j < 4; ++j)
                    acc[i][j] += av[i] * bv[j];
        }
        __syncthreads();
    }
    #pragma unroll
    for (int i = 0; i < 4; ++i) {
        int m = m0 + ty * 4 + i;
        #pragma unroll
        for (int j = 0; j < 4; ++j)
            Ch[(size_t)m * 64 + tx * 4 + j] = acc[i][j];
    }
}

// ---------------- 3: src/dst attention logits (warp per (h,n)) ----------
__global__ void k_srcdst(const float* __restrict__ a, int sel) {
    int wid = threadIdx.x >> 5, lane = threadIdx.x & 31;
    int wg = blockIdx.x * 8 + wid;
    int n = wg & (NN - 1);
    int h = wg >> 12;
    const float* Wh = sel ? g_Whc : g_Wh;
    float* src = sel ? g_srcc : g_src;
    float* dst = sel ? g_dstc : g_dst;
    const float* row = Wh + ((size_t)h * NN + n) * 64;
    const float* ah = a + h * 128;
    float w0 = row[lane], w1 = row[lane + 32];
    float s = w0 * ah[lane]      + w1 * ah[lane + 32];
    float d = w0 * ah[64 + lane] + w1 * ah[96 + lane];
    #pragma unroll
    for (int o = 16; o; o >>= 1) {
        s += __shfl_xor_sync(0xffffffffu, s, o);
        d += __shfl_xor_sync(0xffffffffu, d, o);
    }
    if (lane == 0) { src[h * NN + n] = s; dst[h * NN + n] = d; }
}

// ---------------- 4: sparse GAT softmax + aggregate + ELU ---------------
// warp per (row, head). sel 0: heads -> g_cat; sel 1: att -> fused t1
__global__ void k_gat_aggr(const float* __restrict__ W1, int sel) {
    __shared__ float2 s_wc[8][MAXNBR];
    int wid = threadIdx.x >> 5, lane = threadIdx.x & 31;
    int wg = blockIdx.x * 8 + wid;
    int h, row;
    if (sel) { h = 0; row = wg; } else { h = wg & 3; row = wg >> 2; }
    const float* Wh  = sel ? g_Whc  : g_Wh;
    const float* src = sel ? g_srcc : g_src;
    const float* dst = sel ? g_dstc : g_dst;

    int cnt = g_cnt[row];
    const int* cols = g_cols + row * MAXNBR;
    float si = src[h * NN + row];
    const float* dsth = dst + (size_t)h * NN;

    float e[4]; int cl[4];
    float mx = -1e30f;
    #pragma unroll
    for (int t = 0; t < 4; ++t) {
        int idx = t * 32 + lane;
        if (idx < cnt) {
            int c = cols[idx];
            cl[t] = c;
            float v = si + dsth[c];
            v = v > 0.0f ? v : 0.2f * v;   // LeakyReLU
            e[t] = v;
            mx = fmaxf(mx, v);
        } else { e[t] = -1e30f; cl[t] = 0; }
    }
    #pragma unroll
    for (int o = 16; o; o >>= 1) mx = fmaxf(mx, __shfl_xor_sync(0xffffffffu, mx, o));
    float sum = 0.0f;
    #pragma unroll
    for (int t = 0; t < 4; ++t) {
        e[t] = (t * 32 + lane < cnt) ? __expf(e[t] - mx) : 0.0f;
        sum += e[t];
    }
    #pragma unroll
    for (int o = 16; o; o >>= 1) sum += __shfl_xor_sync(0xffffffffu, sum, o);
    float inv = 1.0f / sum;

    // stage (weight, col) pairs in shared for broadcast reads
    #pragma unroll
    for (int t = 0; t < 4; ++t)
        s_wc[wid][t * 32 + lane] = make_float2(e[t] * inv, __int_as_float(cl[t]));
    __syncwarp();

    const float* Whh = Wh + (size_t)h * NN * 64 + 2 * lane;
    float2 acc0 = make_float2(0.f, 0.f), acc1 = make_float2(0.f, 0.f);
    int j = 0;
    for (; j + 2 <= cnt; j += 2) {
        float2 p0 = s_wc[wid][j], p1 = s_wc[wid][j + 1];
        const float2 v0 = *reinterpret_cast<const float2*>(
            Whh + (size_t)__float_as_int(p0.y) * 64);
        const float2 v1 = *reinterpret_cast<const float2*>(
            Whh + (size_t)__float_as_int(p1.y) * 64);
        acc0.x += p0.x * v0.x; acc0.y += p0.x * v0.y;
        acc1.x += p1.x * v1.x; acc1.y += p1.x * v1.y;
    }
    if (j < cnt) {
        float2 p0 = s_wc[wid][j];
        const float2 v0 = *reinterpret_cast<const float2*>(
            Whh + (size_t)__float_as_int(p0.y) * 64);
        acc0.x += p0.x * v0.x; acc0.y += p0.x * v0.y;
    }
    float a0 = acc0.x + acc1.x;   // feature 2*lane
    float a1 = acc0.y + acc1.y;   // feature 2*lane+1
    a0 = a0 > 0.0f ? a0 : __expf(a0) - 1.0f;   // ELU
    a1 = a1 > 0.0f ? a1 : __expf(a1) - 1.0f;

    if (sel == 0) {
        float* orow = g_cat + (size_t)row * 256 + h * 64 + 2 * lane;
        *reinterpret_cast<float2*>(orow) = make_float2(a0, a1);
    } else {
        // fused: t1[row] = gc_row @ W1   (gc never touches memory)
        float acc = 0.0f;
        #pragma unroll
        for (int k = 0; k < 32; ++k) {
            float w0 = __shfl_sync(0xffffffffu, a0, k);
            float w1 = __shfl_sync(0xffffffffu, a1, k);
            acc += w0 * W1[(2 * k) * 32 + lane] + w1 * W1[(2 * k + 1) * 32 + lane];
        }
        g_t1[(size_t)row * 32 + lane] = acc;
    }
}

// ---------------- 5: h1 = relu(nbrsum(t1)); t23 = h1@[W2|W3] fused ------
__global__ void k_nbr_t23(const float* __restrict__ W2, const float* __restrict__ W3) {
    int wid = threadIdx.x >> 5, lane = threadIdx.x & 31;
    int row = blockIdx.x * 8 + wid;
    int cnt = g_cnt[row];
    const int* cols = g_cols + row * MAXNBR;
    float acc = 0.0f;
    for (int jj = 0; jj < cnt; ++jj) {
        int c = cols[jj];
        acc += g_t1[(size_t)c * 32 + lane];
    }
    float hv = fmaxf(acc, 0.0f);               // h1[row][lane]
    const float* W = (lane < 16) ? W2 : W3;
    int f = lane & 15;
    float acc2 = 0.0f;
    #pragma unroll
    for (int k = 0; k < 32; ++k) {
        float h = __shfl_sync(0xffffffffu, hv, k);
        acc2 += h * W[k * 16 + f];
    }
    g_t23[(size_t)row * 32 + lane] = acc2;
}

// ---------------- 6: mu/logvar = nbrsum, z = eps*exp(lv)+mu, write ------
__global__ void k_final(const float* __restrict__ eps, float* __restrict__ out) {
    int wid = threadIdx.x >> 5, lane = threadIdx.x & 31;
    int row = blockIdx.x * 8 + wid;
    int cnt = g_cnt[row];
    const int* cols = g_cols + row * MAXNBR;
    float acc = 0.0f;
    for (int j = 0; j < cnt; ++j) {
        int c = cols[j];
        acc += g_t23[(size_t)c * 32 + lane];
    }
    float other = __shfl_xor_sync(0xffffffffu, acc, 16);
    size_t NNq = (size_t)NN * NN;
    if (lane < 16) {
        out[NNq + (size_t)row * 16 + lane] = acc;                     // mu
        float zz = eps[(size_t)row * 16 + lane] * __expf(other) + acc;
        g_z[(size_t)row * 16 + lane] = zz;
    } else {
        out[NNq + (size_t)NN * 16 + (size_t)row * 16 + (lane - 16)] = acc; // logvar
    }
}

// ---------------- 7: adj_rec = z @ z^T (64x64 tiles, float4 stores) -----
__global__ void k_adjrec(float* __restrict__ out) {
    __shared__ float zi[64 * 17];
    __shared__ float zj[64 * 17];
    int i0 = blockIdx.y * 64, j0 = blockIdx.x * 64;
    int tid = threadIdx.x;
    for (int l = tid; l < 1024; l += 256) {
        int r = l >> 4, k = l & 15;
        zi[r * 17 + k] = g_z[(size_t)(i0 + r) * 16 + k];
        zj[r * 17 + k] = g_z[(size_t)(j0 + r) * 16 + k];
    }
    __syncthreads();
    int ty = tid >> 4, tx = tid & 15;
    float acc[4][4] = {};
    #pragma unroll
    for (int k = 0; k < 16; ++k) {
        float av[4], bv[4];
        #pragma unroll
        for (int i = 0; i < 4; ++i) av[i] = zi[(ty * 4 + i) * 17 + k];
        #pragma unroll
        for (int j = 0; j < 4; ++j) bv[j] = zj[(tx * 4 + j) * 17 + k];
        #pragma unroll
        for (int i = 0; i < 4; ++i)
            #pragma unroll
            for (int j = 0; j < 4; ++j)
                acc[i][j] += av[i] * bv[j];
    }
    #pragma unroll
    for (int i = 0; i < 4; ++i) {
        float4 v = make_float4(acc[i][0], acc[i][1], acc[i][2], acc[i][3]);
        *reinterpret_cast<float4*>(out + (size_t)(i0 + ty * 4 + i) * NN + j0 + tx * 4) = v;
    }
}

// ---------------- launch ------------------------------------------------
extern "C" void kernel_launch(void* const* d_in, const int* in_sizes, int n_in,
                              void* d_out, int out_size) {
    const float* x       = (const float*)d_in[0];
    const float* adj     = (const float*)d_in[1];
    const float* W_heads = (const float*)d_in[2];
    const float* a_heads = (const float*)d_in[3];
    const float* W_att   = (const float*)d_in[4];
    const float* a_att   = (const float*)d_in[5];
    const float* W1      = (const float*)d_in[6];
    const float* W2      = (const float*)d_in[7];
    const float* W3      = (const float*)d_in[8];
    const float* eps     = (const float*)d_in[9];
    float* out = (float*)d_out;
    (void)in_sizes; (void)n_in; (void)out_size;

    k_build_csr<<<NN / 8, 256>>>(adj);
    k_gemm64<<<dim3(NN / 64, HH), 256>>>(x, W_heads, DD, 0);
    k_srcdst<<<(NN * HH) / 8, 256>>>(a_heads, 0);
    k_gat_aggr<<<(NN * HH) / 8, 256>>>(W1, 0);
    k_gemm64<<<dim3(NN / 64, 1), 256>>>(nullptr, W_att, HH * F1V, 1);
    k_srcdst<<<NN / 8, 256>>>(a_att, 1);
    k_gat_aggr<<<NN / 8, 256>>>(W1, 1);
    k_nbr_t23<<<NN / 8, 256>>>(W2, W3);
    k_final<<<NN / 8, 256>>>(eps, out);
    k_adjrec<<<dim3(NN / 64, NN / 64), 256>>>(out);
}